// round 13
// baseline (speedup 1.0000x reference)
#include <cuda_runtime.h>
#include <cuda_fp16.h>
#include <math.h>
#include <stdint.h>

typedef __half h16;

// ---------------- problem dims ----------------
#define LY 4
#define BN 4
#define T_ 1024
#define TC 1024
#define T1 2048
#define D_ 384
#define DK 256
#define FF 1536
#define TTMIX 0.1f
#define LN_EPS 1e-5f

#define NX   (BN*T_*D_)
#define NAT  (BN*T_*T1)
#define NQX  (BN*T_*DK)
#define NH_  (BN*T_*FF)
#define NMEM (BN*T1*DK)
#define NOC  (LY*BN*TC*D_)
#define NSCT (BN*T1*TC)
#define NM2  (BN*T1*D_)
#define NWQT (LY*D_*D_)
#define NWKT (LY*D_*DK)
#define NW1  (LY*FF*D_)

// ---------------- scratch ----------------
__device__ __align__(128) float g_x[NX];
__device__ __align__(128) float g_m2slab[2*NM2], g_z1slab[4*NQX];
__device__ __align__(128) float g_y2slab[3*NX], g_zslab[2*NX];
__device__ __align__(128) float g_pvec[LY*DK], g_wvec[LY*BN*T1];
__device__ __align__(128) h16 g_atth[NAT], g_mixh[NAT];
__device__ __align__(128) h16 g_xh[NX], g_qxh[NQX];
__device__ __align__(128) h16 g_mh[NMEM], g_mth[NMEM];
__device__ __align__(128) h16 g_unh[NX], g_knh[NX];
__device__ __align__(128) h16 g_m2h[LY*NM2];
__device__ __align__(128) h16 g_blh[NAT];
__device__ __align__(128) h16 g_hh[NH_];
__device__ __align__(128) h16 g_oh[NOC], g_sth[NSCT];
__device__ __align__(128) h16 g_wqth[NWQT], g_wkth[NWKT], g_wqkth[NWKT];
__device__ __align__(128) h16 g_wvh[NWKT], g_wnh[NWQT], g_wuh[NWQT];
__device__ __align__(128) h16 g_w1h[NW1], g_w2h[NW1];

// ---------------- helpers ----------------
__device__ __forceinline__ uint32_t u32smem(const void* p) {
    uint32_t a;
    asm("{ .reg .u64 t; cvta.to.shared.u64 t, %1; cvt.u32.u64 %0, t; }" : "=r"(a) : "l"(p));
    return a;
}
__device__ __forceinline__ void cpa16(uint32_t s, const void* g) {
    asm volatile("cp.async.cg.shared.global [%0], [%1], 16;" :: "r"(s), "l"(g));
}
#define CP_COMMIT() asm volatile("cp.async.commit_group;" ::: "memory")
#define CP_WAIT(n)  asm volatile("cp.async.wait_group %0;" :: "n"(n) : "memory")

__device__ __forceinline__ void ldsm_x4(uint32_t& r0, uint32_t& r1, uint32_t& r2,
                                        uint32_t& r3, uint32_t a) {
    asm volatile("ldmatrix.sync.aligned.m8n8.x4.shared.b16 {%0,%1,%2,%3}, [%4];"
                 : "=r"(r0), "=r"(r1), "=r"(r2), "=r"(r3) : "r"(a));
}
__device__ __forceinline__ void mma16816(float* d, const uint32_t* a, const uint32_t* b) {
    asm volatile(
        "mma.sync.aligned.m16n8k16.row.col.f32.f16.f16.f32 "
        "{%0,%1,%2,%3},{%4,%5,%6,%7},{%8,%9},{%0,%1,%2,%3};"
        : "+f"(d[0]), "+f"(d[1]), "+f"(d[2]), "+f"(d[3])
        : "r"(a[0]), "r"(a[1]), "r"(a[2]), "r"(a[3]), "r"(b[0]), "r"(b[1]));
}

// ---------------- fp16 tensor GEMM: C = alpha*A@B^T (+bias)(+relu) -----------
#define STAGES 3
#define STAGE_BYTES 32768

__global__ void __launch_bounds__(256, 2)
mma_gemm(const h16* __restrict__ A, const h16* __restrict__ B,
         const float* __restrict__ bias, float alpha, int flags,
         float* __restrict__ Cf, h16* __restrict__ Ch,
         int M, int N, int K, long long sA, long long sB, long long sC,
         int kspl, long long slabStride)
{
    extern __shared__ char sm[];
    const int tid = threadIdx.x, lane = tid & 31, wid = tid >> 5;
    const int wm = wid & 3, wn = wid >> 2;
    const int zb = blockIdx.z;
    const long long bz = zb / kspl;
    const int ks = zb - (int)bz * kspl;
    const int Kc = K / kspl;
    const int bm0 = blockIdx.y << 7, bn0 = blockIdx.x << 7;

    const char* gsrc[2] = {
        (const char*)(A + bz * sA + (long long)bm0 * K),
        (const char*)(B + bz * sB + (long long)bn0 * K) };
    const uint32_t sbase = u32smem(sm);
    const long long rowbytes = (long long)K * 2;

    float acc[2][8][4];
    #pragma unroll
    for (int i = 0; i < 2; i++)
        #pragma unroll
        for (int j = 0; j < 8; j++)
            #pragma unroll
            for (int q = 0; q < 4; q++) acc[i][j][q] = 0.f;

    const int nc = Kc >> 6;
    const int kbase = ks * Kc;

    auto load_stage = [&](int buf, int k0) {
        uint32_t sb = sbase + buf * STAGE_BYTES;
        #pragma unroll
        for (int t = 0; t < 2; t++) {
            uint32_t ab = sb + t * 16384;
            const char* g = gsrc[t];
            #pragma unroll
            for (int i = 0; i < 4; i++) {
                int idx = i * 256 + tid;
                int r = idx >> 3, c = idx & 7;
                uint32_t so = ab + r * 128 + ((c ^ (r & 7)) << 4);
                cpa16(so, g + (long long)r * rowbytes + (long long)k0 * 2 + c * 16);
            }
        }
    };

    auto compute = [&](int buf) {
        uint32_t sbA = sbase + buf * STAGE_BYTES;
        uint32_t sbB = sbA + 16384;
        #pragma unroll
        for (int s = 0; s < 4; s++) {
            uint32_t a[2][4];
            #pragma unroll
            for (int mi = 0; mi < 2; mi++) {
                int row = wm * 32 + mi * 16 + (lane & 15);
                int c = 2 * s + (lane >> 4);
                uint32_t off = row * 128 + ((c ^ (row & 7)) << 4);
                ldsm_x4(a[mi][0], a[mi][1], a[mi][2], a[mi][3], sbA + off);
            }
            #pragma unroll
            for (int nj = 0; nj < 4; nj++) {
                int row = wn * 64 + nj * 16 + (lane & 15);
                int c = 2 * s + (lane >> 4);
                uint32_t off = row * 128 + ((c ^ (row & 7)) << 4);
                uint32_t r0, r1, r2, r3;
                ldsm_x4(r0, r1, r2, r3, sbB + off);
                uint32_t b0[2] = {r0, r2}, b1[2] = {r1, r3};
                #pragma unroll
                for (int mi = 0; mi < 2; mi++) {
                    mma16816(acc[mi][2*nj],   a[mi], b0);
                    mma16816(acc[mi][2*nj+1], a[mi], b1);
                }
            }
        }
    };

    #pragma unroll
    for (int s = 0; s < STAGES - 1; s++) {
        if (s < nc) load_stage(s, kbase + s * 64);
        CP_COMMIT();
    }
    int buf = 0, nxt = STAGES - 1;
    for (int c = 0; c < nc; c++) {
        CP_WAIT(STAGES - 2);
        __syncthreads();
        if (c + STAGES - 1 < nc) {
            load_stage(nxt, kbase + (c + STAGES - 1) * 64);
            CP_COMMIT();
        } else {
            CP_COMMIT();
        }
        compute(buf);
        if (++buf == STAGES) buf = 0;
        if (++nxt == STAGES) nxt = 0;
    }

    float* Cfo = Cf ? Cf + (long long)ks * slabStride : nullptr;
    const int rl = lane >> 2, cl = (lane & 3) * 2;
    #pragma unroll
    for (int mi = 0; mi < 2; mi++) {
        #pragma unroll
        for (int hf = 0; hf < 2; hf++) {
            const long long grow = bm0 + wm * 32 + mi * 16 + rl + hf * 8;
            float brow = 0.f;
            if (bias && (flags & 2)) brow = bias[grow];
            const long long base = bz * sC + grow * (long long)N + bn0 + wn * 64;
            #pragma unroll
            for (int nb = 0; nb < 8; nb++) {
                const int coff = nb * 8 + cl;
                float v0 = acc[mi][nb][hf*2+0] * alpha;
                float v1 = acc[mi][nb][hf*2+1] * alpha;
                if (bias) {
                    if (flags & 2) { v0 += brow; v1 += brow; }
                    else {
                        const long long gcol = bn0 + wn * 64 + coff;
                        v0 += bias[gcol]; v1 += bias[gcol + 1];
                    }
                }
                if (flags & 1) { v0 = fmaxf(v0, 0.f); v1 = fmaxf(v1, 0.f); }
                if (Cfo) *reinterpret_cast<float2*>(Cfo + base + coff) = make_float2(v0, v1);
                if (Ch) {
                    __half2 p = __floats2half2_rn(v0, v1);
                    *reinterpret_cast<uint32_t*>(Ch + base + coff) =
                        *reinterpret_cast<uint32_t*>(&p);
                }
            }
        }
    }
}

// ---------------- fp32 -> fp16 ----------------
__global__ void cvt16(const float* __restrict__ in, h16* __restrict__ out, long long n4)
{
    long long i = blockIdx.x * (long long)blockDim.x + threadIdx.x;
    if (i >= n4) return;
    float4 v = reinterpret_cast<const float4*>(in)[i];
    __half2 a = __floats2half2_rn(v.x, v.y);
    __half2 b = __floats2half2_rn(v.z, v.w);
    reinterpret_cast<uint2*>(out)[i] = make_uint2(*(uint32_t*)&a, *(uint32_t*)&b);
}

// ---------------- sum ns fp32 slabs -> fp16 ----------------
__global__ void reduce16(const float* __restrict__ slabs, long long sstride4,
                         int ns, h16* __restrict__ out, long long n4)
{
    long long i = blockIdx.x * (long long)blockDim.x + threadIdx.x;
    if (i >= n4) return;
    const float4* p = reinterpret_cast<const float4*>(slabs);
    float4 v = p[i];
    for (int s = 1; s < ns; s++) {
        float4 t = p[i + s * sstride4];
        v.x += t.x; v.y += t.y; v.z += t.z; v.w += t.w;
    }
    __half2 a = __floats2half2_rn(v.x, v.y);
    __half2 b = __floats2half2_rn(v.z, v.w);
    reinterpret_cast<uint2*>(out)[i] = make_uint2(*(uint32_t*)&a, *(uint32_t*)&b);
}

// ---------------- transpose: [batch,R,C] f32 -> [batch,C,R] fp16 -------------
__global__ void transpose16(const float* __restrict__ in, h16* __restrict__ out,
                            int R, int C)
{
    __shared__ float tile[32][33];
    const long long b = blockIdx.z;
    const int c0 = blockIdx.x << 5;
    const int r0 = blockIdx.y << 5;
    const float* ib = in + b * (long long)R * C;
    const int tx = threadIdx.x, ty = threadIdx.y;
    #pragma unroll
    for (int i = 0; i < 4; i++)
        tile[ty + 8*i][tx] = ib[(long long)(r0 + ty + 8*i) * C + c0 + tx];
    __syncthreads();
    h16* ob = out + b * (long long)R * C;
    #pragma unroll
    for (int i = 0; i < 4; i++) {
        float v = tile[tx][ty + 8*i];
        ob[(long long)(c0 + ty + 8*i) * R + r0 + tx] = __float2half_rn(v);
    }
}

// ---------------- batched bias-fold vectors (all layers) ----------------
__global__ void pvec_all(const float* __restrict__ Wk, const float* __restrict__ bq,
                         float* __restrict__ pvec)
{
    int l = blockIdx.x, dk = threadIdx.x;
    const float* Wkl = Wk + (long long)l * D_ * DK;
    const float* bql = bq + (long long)l * D_;
    float s = 0.f;
    for (int e = 0; e < D_; e++) s += bql[e] * Wkl[(long long)e * DK + dk];
    pvec[l * DK + dk] = s;
}
__global__ void wvec_all(const float* __restrict__ mem, const float* __restrict__ pvec,
                         float* __restrict__ w, float scale)
{
    const int per = BN * T1 / 256;
    int l = blockIdx.x / per;
    int i = (blockIdx.x - l * per) * 256 + threadIdx.x;
    const float* m = mem + (long long)i * DK;
    const float* pv = pvec + l * DK;
    float s = 0.f;
    #pragma unroll 8
    for (int dk = 0; dk < DK; dk++) s += m[dk] * pv[dk];
    w[(long long)l * BN * T1 + i] = s * scale;
}

// ---------------- reductions ----------------
__device__ __forceinline__ float warpMax(float v) {
    #pragma unroll
    for (int o = 16; o > 0; o >>= 1) v = fmaxf(v, __shfl_xor_sync(0xffffffffu, v, o));
    return v;
}
__device__ __forceinline__ float warpSum(float v) {
    #pragma unroll
    for (int o = 16; o > 0; o >>= 1) v += __shfl_xor_sync(0xffffffffu, v, o);
    return v;
}
__device__ __forceinline__ float blockMax(float v) {
    __shared__ float sh[8];
    v = warpMax(v);
    __syncthreads();
    if ((threadIdx.x & 31) == 0) sh[threadIdx.x >> 5] = v;
    __syncthreads();
    float r = -1e30f;
    int nw = blockDim.x >> 5;
    #pragma unroll
    for (int i = 0; i < 8; i++) if (i < nw) r = fmaxf(r, sh[i]);
    return r;
}
__device__ __forceinline__ float blockSum(float v) {
    __shared__ float sh[8];
    v = warpSum(v);
    __syncthreads();
    if ((threadIdx.x & 31) == 0) sh[threadIdx.x >> 5] = v;
    __syncthreads();
    float r = 0.0f;
    int nw = blockDim.x >> 5;
    #pragma unroll
    for (int i = 0; i < 8; i++) if (i < nw) r += sh[i];
    return r;
}

// ---------------- dual softmax + blend (fp16 logits in) -> fp16 --------------
__global__ void __launch_bounds__(256)
softmax_blend(const h16* __restrict__ mixed, const h16* __restrict__ att,
              const float* __restrict__ w, h16* __restrict__ out)
{
    const long long base = (long long)blockIdx.x * T1;
    const int b = blockIdx.x >> 10;
    const int tid = threadIdx.x;
    float mv[8], av[8];
    float m1 = -1e30f, m2 = -1e30f;
    #pragma unroll
    for (int i = 0; i < 8; i++) {
        int c = tid + i * 256;
        mv[i] = __half2float(mixed[base + c]);
        av[i] = __half2float(att[base + c]) + w[(long long)b * T1 + c];
        m1 = fmaxf(m1, mv[i]);
        m2 = fmaxf(m2, av[i]);
    }
    m1 = blockMax(m1);
    m2 = blockMax(m2);
    float s1 = 0.f, s2 = 0.f;
    #pragma unroll
    for (int i = 0; i < 8; i++) {
        mv[i] = __expf(mv[i] - m1);
        av[i] = __expf(av[i] - m2);
        s1 += mv[i]; s2 += av[i];
    }
    s1 = blockSum(s1);
    s2 = blockSum(s2);
    const float r1 = TTMIX / s1, r2 = (1.0f - TTMIX) / s2;
    #pragma unroll
    for (int i = 0; i < 8; i++) {
        int c = tid + i * 256;
        out[base + c] = __float2half_rn(mv[i] * r1 + av[i] * r2);
    }
}

// ---------------- residual add + LayerNorm -> fp32 + fp16 --------------------
__global__ void __launch_bounds__(128)
add_ln(float* __restrict__ x, const float* __restrict__ slabs, int ns,
       long long sstride, const float* __restrict__ bias2,
       const float* __restrict__ g, const float* __restrict__ b,
       h16* __restrict__ xh)
{
    const long long base = (long long)blockIdx.x * D_;
    const int tid = threadIdx.x;
    float v[3];
    #pragma unroll
    for (int i = 0; i < 3; i++) {
        int c = tid + i * 128;
        float t = x[base + c];
        for (int s = 0; s < ns; s++) t += slabs[s * sstride + base + c];
        if (bias2) t += bias2[c];
        v[i] = t;
    }
    float s = v[0] + v[1] + v[2];
    s = blockSum(s);
    const float mean = s * (1.0f / D_);
    float q = 0.f;
    #pragma unroll
    for (int i = 0; i < 3; i++) { float d = v[i] - mean; q += d * d; }
    q = blockSum(q);
    const float rstd = rsqrtf(q * (1.0f / D_) + LN_EPS);
    #pragma unroll
    for (int i = 0; i < 3; i++) {
        int c = tid + i * 128;
        float o = (v[i] - mean) * rstd * g[c] + b[c];
        x[base + c] = o;
        xh[base + c] = __float2half_rn(o);
    }
}

// ---------------- host ----------------
#define SMEM_DYN (STAGES * STAGE_BYTES)
#define SYM(p, s) do { void* _t; cudaGetSymbolAddress(&_t, s); p = (decltype(p))_t; } while (0)

static void split(const float* in, h16* out, long long n, cudaStream_t st) {
    long long n4 = n / 4;
    cvt16<<<(unsigned)((n4 + 255) / 256), 256, 0, st>>>(in, out, n4);
}
static void gemm(const h16* A, const h16* B, const float* bias, float alpha,
                 int flags, float* Cf, h16* Ch,
                 int M, int N, int K, int batch,
                 long long sA, long long sB, long long sC, cudaStream_t st,
                 int kspl = 1, long long slabStride = 0) {
    dim3 g(N / 128, M / 128, batch * kspl);
    mma_gemm<<<g, 256, SMEM_DYN, st>>>(A, B, bias, alpha, flags, Cf, Ch,
                                       M, N, K, sA, sB, sC, kspl, slabStride);
}
static void transpose_split(const float* in, h16* out, int R, int C, int batch,
                            cudaStream_t st) {
    dim3 g(C / 32, R / 32, batch), b(32, 8);
    transpose16<<<g, b, 0, st>>>(in, out, R, C);
}

extern "C" void kernel_launch(void* const* d_in, const int* in_sizes, int n_in,
                              void* d_out, int out_size)
{
    (void)in_sizes; (void)n_in; (void)out_size;
    const float* tgt     = (const float*)d_in[0];
    const float* memory  = (const float*)d_in[1];
    const float* score_c = (const float*)d_in[2];
    const float* out_c   = (const float*)d_in[3];
    const float* Wq  = (const float*)d_in[4];
    const float* bq  = (const float*)d_in[5];
    const float* Wk  = (const float*)d_in[6];
    const float* Wv  = (const float*)d_in[8];
    const float* bv  = (const float*)d_in[9];
    const float* Wkn = (const float*)d_in[10];
    const float* bkn = (const float*)d_in[11];
    const float* Wun = (const float*)d_in[12];
    const float* bun = (const float*)d_in[13];
    const float* W1  = (const float*)d_in[14];
    const float* b1  = (const float*)d_in[15];
    const float* W2  = (const float*)d_in[16];
    const float* b2  = (const float*)d_in[17];
    const float* g1  = (const float*)d_in[18];
    const float* be1 = (const float*)d_in[19];
    const float* g2  = (const float*)d_in[20];
    const float* be2 = (const float*)d_in[21];

    float *x, *m2slab, *z1slab, *y2slab, *zslab, *pvec, *wvec;
    SYM(x, g_x);
    SYM(m2slab, g_m2slab); SYM(z1slab, g_z1slab);
    SYM(y2slab, g_y2slab); SYM(zslab, g_zslab);
    SYM(pvec, g_pvec); SYM(wvec, g_wvec);
    h16 *atth,*mixh,*xh,*qxh,*mh,*mth,*unh,*knh,*m2h,*blh,*hh,*oh,*sth;
    h16 *wqth,*wkth,*wqkth,*wvh,*wnh,*wuh,*w1h,*w2h;
    SYM(atth,g_atth); SYM(mixh,g_mixh);
    SYM(xh,g_xh); SYM(qxh,g_qxh); SYM(mh,g_mh); SYM(mth,g_mth);
    SYM(unh,g_unh); SYM(knh,g_knh); SYM(m2h,g_m2h); SYM(blh,g_blh);
    SYM(hh,g_hh); SYM(oh,g_oh); SYM(sth,g_sth);
    SYM(wqth,g_wqth); SYM(wkth,g_wkth); SYM(wqkth,g_wqkth);
    SYM(wvh,g_wvh); SYM(wnh,g_wnh); SYM(wuh,g_wuh);
    SYM(w1h,g_w1h); SYM(w2h,g_w2h);

    cudaFuncSetAttribute(mma_gemm, cudaFuncAttributeMaxDynamicSharedMemorySize, SMEM_DYN);

    // ---- streams/events (created once) ----
    static cudaStream_t s1 = nullptr, s2 = nullptr;
    static cudaEvent_t e0 = nullptr, s1done = nullptr;
    static cudaEvent_t ev_m2t[LY], ev_att[LY], ev_x[LY];
    if (!s1) {
        cudaStreamCreateWithFlags(&s1, cudaStreamNonBlocking);
        cudaStreamCreateWithFlags(&s2, cudaStreamNonBlocking);
        cudaEventCreateWithFlags(&e0, cudaEventDisableTiming);
        cudaEventCreateWithFlags(&s1done, cudaEventDisableTiming);
        for (int l = 0; l < LY; l++) {
            cudaEventCreateWithFlags(&ev_m2t[l], cudaEventDisableTiming);
            cudaEventCreateWithFlags(&ev_att[l], cudaEventDisableTiming);
            cudaEventCreateWithFlags(&ev_x[l], cudaEventDisableTiming);
        }
    }

    const float scale = 1.0f / sqrtf((float)D_);
    cudaStream_t s0 = 0;

    // ---- prologue (main stream; r12 structure) ----
    cudaMemcpyAsync(x, tgt, (size_t)NX * 4, cudaMemcpyDeviceToDevice, s0);
    split(tgt, xh, NX, s0);
    split(memory, mh, NMEM, s0);
    split(out_c, oh, NOC, s0);
    split(Wv, wvh, NWKT, s0);
    split(Wkn, wnh, NWQT, s0);
    split(Wun, wuh, NWQT, s0);
    split(W1, w1h, NW1, s0);
    split(W2, w2h, NW1, s0);
    transpose_split(memory, mth, T1, DK, BN, s0);
    transpose_split(Wq, wqth, D_, D_, LY, s0);
    transpose_split(Wk, wkth, D_, DK, LY, s0);
    gemm(wkth, wqth, nullptr, 1.f, 0, nullptr, wqkth,
         DK, D_, D_, LY, (long long)DK*D_, (long long)D_*D_, (long long)DK*D_, s0);
    pvec_all<<<LY, DK, 0, s0>>>(Wk, bq, pvec);
    wvec_all<<<LY * (BN*T1/256), 256, 0, s0>>>(memory, pvec, wvec, scale);
    cudaEventRecord(e0, s0);

    // ---- stream s1: x-independent precompute (all layers; gated on e0) ----
    cudaStreamWaitEvent(s1, e0, 0);
    for (int l = 0; l < LY; l++) {
        const long long oq = (long long)l * D_ * D_;
        gemm(wnh + oq, oh + (long long)l*BN*TC*D_, bkn + (long long)l*D_, 1.f, 2,
             nullptr, knh, D_, TC, D_, BN, 0, (long long)TC*D_, (long long)D_*TC, s1);
        transpose_split(score_c + (long long)l*BN*TC*T1, sth, TC, T1, BN, s1);
        gemm(sth, knh, nullptr, scale, 0, m2slab, nullptr,
             T1, D_, TC, BN, (long long)T1*TC, (long long)D_*TC, (long long)T1*D_,
             s1, 2, (long long)NM2);
        reduce16<<<(NM2/4 + 255)/256, 256, 0, s1>>>(
            m2slab, NM2/4, 2, m2h + (long long)l*NM2, NM2/4);
        cudaEventRecord(ev_m2t[l], s1);
    }
    cudaEventRecord(s1done, s1);

    // ---- main + s2 per-layer ----
    for (int l = 0; l < LY; l++) {
        const long long oq = (long long)l * D_ * D_;
        const long long ok = (long long)l * D_ * DK;
        const long long o1 = (long long)l * FF * D_;

        // s2: qx -> att (fp16 logits out)
        cudaStreamWaitEvent(s2, (l == 0) ? e0 : ev_x[l], 0);
        gemm(xh, wqkth + ok, nullptr, 1.f, 0, nullptr, qxh,
             BN*T_, DK, D_, 1, 0, 0, 0, s2);
        gemm(qxh, mh, nullptr, scale, 0, nullptr, atth,
             T_, T1, DK, BN, (long long)T_*DK, (long long)T1*DK, (long long)T_*T1, s2);
        cudaEventRecord(ev_att[l], s2);

        // main: unk
        gemm(xh, wuh + oq, bun + (long long)l*D_, 1.f, 0, nullptr, unh,
             BN*T_, D_, D_, 1, 0, 0, 0, s0);
        // main: mixed (fp16 logits out; needs M2T[l])
        cudaStreamWaitEvent(s0, ev_m2t[l], 0);
        gemm(unh, m2h + (long long)l*NM2, nullptr, 1.f, 0, nullptr, mixh,
             T_, T1, D_, BN, (long long)T_*D_, (long long)T1*D_, (long long)T_*T1, s0);
        // main: softmax blend (needs att)
        cudaStreamWaitEvent(s0, ev_att[l], 0);
        softmax_blend<<<BN*T_, 256, 0, s0>>>(mixh, atth, wvec + (long long)l*BN*T1, blh);
        // z1 = blended @ memT^T, split-K=4
        gemm(blh, mth, nullptr, 1.f, 0, z1slab, nullptr,
             T_, DK, T1, BN, (long long)T_*T1, (long long)DK*T1, (long long)T_*DK,
             s0, 4, (long long)NQX);
        reduce16<<<(NQX/4 + 255)/256, 256, 0, s0>>>(z1slab, NQX/4, 4, qxh, NQX/4);
        // z = z1 @ Wv^T, split-K=2 (bv added in add_ln)
        gemm(qxh, wvh + ok, nullptr, 1.f, 0, zslab, nullptr,
             BN*T_, D_, DK, 1, 0, 0, 0, s0, 2, (long long)NX);
        add_ln<<<BN*T_, 128, 0, s0>>>(x, zslab, 2, (long long)NX, bv + (long long)l*D_,
                                      g1 + (long long)l*D_, be1 + (long long)l*D_, xh);
        // h = relu(x @ W1^T + b1)
        gemm(xh, w1h + o1, b1 + (long long)l*FF, 1.f, 1, nullptr, hh,
             BN*T_, FF, D_, 1, 0, 0, 0, s0);
        // y2 = h @ W2^T, split-K=3 (b2 added in add_ln)
        gemm(hh, w2h + o1, nullptr, 1.f, 0, y2slab, nullptr,
             BN*T_, D_, FF, 1, 0, 0, 0, s0, 3, (long long)NX);
        add_ln<<<BN*T_, 128, 0, s0>>>(x, y2slab, 3, (long long)NX, b2 + (long long)l*D_,
                                      g2 + (long long)l*D_, be2 + (long long)l*D_, xh);
        if (l + 1 < LY) cudaEventRecord(ev_x[l + 1], s0);
    }

    cudaStreamWaitEvent(s0, s1done, 0);
    cudaMemcpyAsync(d_out, x, (size_t)NX * 4, cudaMemcpyDeviceToDevice, s0);
}

// round 14
// speedup vs baseline: 1.0026x; 1.0026x over previous
#include <cuda_runtime.h>
#include <cuda_fp16.h>
#include <math.h>
#include <stdint.h>

typedef __half h16;

// ---------------- problem dims ----------------
#define LY 4
#define BN 4
#define T_ 1024
#define TC 1024
#define T1 2048
#define D_ 384
#define DK 256
#define FF 1536
#define TTMIX 0.1f
#define LN_EPS 1e-5f

#define NX   (BN*T_*D_)
#define NAT  (BN*T_*T1)
#define NQX  (BN*T_*DK)
#define NH_  (BN*T_*FF)
#define NMEM (BN*T1*DK)
#define NOC  (LY*BN*TC*D_)
#define NSCT (BN*T1*TC)
#define NM2  (BN*T1*D_)
#define NWQT (LY*D_*D_)
#define NWKT (LY*D_*DK)
#define NW1  (LY*FF*D_)

// ---------------- scratch ----------------
__device__ __align__(128) float g_x[NX], g_att[NAT], g_mix[NAT];
__device__ __align__(128) float g_m2slab[2*NM2], g_z1slab[4*NQX];
__device__ __align__(128) float g_y2slab[3*NX], g_zslab[2*NX];
__device__ __align__(128) float g_pvec[LY*DK], g_wvec[LY*BN*T1];
__device__ __align__(128) h16 g_xh[NX], g_qxh[NQX];
__device__ __align__(128) h16 g_mh[NMEM], g_mth[NMEM];
__device__ __align__(128) h16 g_unh[NX], g_knh[NX];
__device__ __align__(128) h16 g_m2h[LY*NM2];
__device__ __align__(128) h16 g_blh[NAT];
__device__ __align__(128) h16 g_hh[NH_];
__device__ __align__(128) h16 g_oh[NOC], g_sth[NSCT];
__device__ __align__(128) h16 g_wqth[NWQT], g_wkth[NWKT], g_wqkth[NWKT];
__device__ __align__(128) h16 g_wvh[NWKT], g_wnh[NWQT], g_wuh[NWQT];
__device__ __align__(128) h16 g_w1h[NW1], g_w2h[NW1];

// ---------------- helpers ----------------
__device__ __forceinline__ uint32_t u32smem(const void* p) {
    uint32_t a;
    asm("{ .reg .u64 t; cvta.to.shared.u64 t, %1; cvt.u32.u64 %0, t; }" : "=r"(a) : "l"(p));
    return a;
}
__device__ __forceinline__ void cpa16(uint32_t s, const void* g) {
    asm volatile("cp.async.cg.shared.global [%0], [%1], 16;" :: "r"(s), "l"(g));
}
#define CP_COMMIT() asm volatile("cp.async.commit_group;" ::: "memory")
#define CP_WAIT(n)  asm volatile("cp.async.wait_group %0;" :: "n"(n) : "memory")

__device__ __forceinline__ void ldsm_x4(uint32_t& r0, uint32_t& r1, uint32_t& r2,
                                        uint32_t& r3, uint32_t a) {
    asm volatile("ldmatrix.sync.aligned.m8n8.x4.shared.b16 {%0,%1,%2,%3}, [%4];"
                 : "=r"(r0), "=r"(r1), "=r"(r2), "=r"(r3) : "r"(a));
}
__device__ __forceinline__ void mma16816(float* d, const uint32_t* a, const uint32_t* b) {
    asm volatile(
        "mma.sync.aligned.m16n8k16.row.col.f32.f16.f16.f32 "
        "{%0,%1,%2,%3},{%4,%5,%6,%7},{%8,%9},{%0,%1,%2,%3};"
        : "+f"(d[0]), "+f"(d[1]), "+f"(d[2]), "+f"(d[3])
        : "r"(a[0]), "r"(a[1]), "r"(a[2]), "r"(a[3]), "r"(b[0]), "r"(b[1]));
}

// ---------------- fp16 tensor GEMM 128x128: C = alpha*A@B^T (+bias)(+relu) ---
#define STAGES 3
#define STAGE_BYTES 32768

__global__ void __launch_bounds__(256, 2)
mma_gemm(const h16* __restrict__ A, const h16* __restrict__ B,
         const float* __restrict__ bias, float alpha, int flags,
         float* __restrict__ Cf, h16* __restrict__ Ch,
         int M, int N, int K, long long sA, long long sB, long long sC,
         int kspl, long long slabStride)
{
    extern __shared__ char sm[];
    const int tid = threadIdx.x, lane = tid & 31, wid = tid >> 5;
    const int wm = wid & 3, wn = wid >> 2;
    const int zb = blockIdx.z;
    const long long bz = zb / kspl;
    const int ks = zb - (int)bz * kspl;
    const int Kc = K / kspl;
    const int bm0 = blockIdx.y << 7, bn0 = blockIdx.x << 7;

    const char* gsrc[2] = {
        (const char*)(A + bz * sA + (long long)bm0 * K),
        (const char*)(B + bz * sB + (long long)bn0 * K) };
    const uint32_t sbase = u32smem(sm);
    const long long rowbytes = (long long)K * 2;

    float acc[2][8][4];
    #pragma unroll
    for (int i = 0; i < 2; i++)
        #pragma unroll
        for (int j = 0; j < 8; j++)
            #pragma unroll
            for (int q = 0; q < 4; q++) acc[i][j][q] = 0.f;

    const int nc = Kc >> 6;
    const int kbase = ks * Kc;

    auto load_stage = [&](int buf, int k0) {
        uint32_t sb = sbase + buf * STAGE_BYTES;
        #pragma unroll
        for (int t = 0; t < 2; t++) {
            uint32_t ab = sb + t * 16384;
            const char* g = gsrc[t];
            #pragma unroll
            for (int i = 0; i < 4; i++) {
                int idx = i * 256 + tid;
                int r = idx >> 3, c = idx & 7;
                uint32_t so = ab + r * 128 + ((c ^ (r & 7)) << 4);
                cpa16(so, g + (long long)r * rowbytes + (long long)k0 * 2 + c * 16);
            }
        }
    };

    auto compute = [&](int buf) {
        uint32_t sbA = sbase + buf * STAGE_BYTES;
        uint32_t sbB = sbA + 16384;
        #pragma unroll
        for (int s = 0; s < 4; s++) {
            uint32_t a[2][4];
            #pragma unroll
            for (int mi = 0; mi < 2; mi++) {
                int row = wm * 32 + mi * 16 + (lane & 15);
                int c = 2 * s + (lane >> 4);
                uint32_t off = row * 128 + ((c ^ (row & 7)) << 4);
                ldsm_x4(a[mi][0], a[mi][1], a[mi][2], a[mi][3], sbA + off);
            }
            #pragma unroll
            for (int nj = 0; nj < 4; nj++) {
                int row = wn * 64 + nj * 16 + (lane & 15);
                int c = 2 * s + (lane >> 4);
                uint32_t off = row * 128 + ((c ^ (row & 7)) << 4);
                uint32_t r0, r1, r2, r3;
                ldsm_x4(r0, r1, r2, r3, sbB + off);
                uint32_t b0[2] = {r0, r2}, b1[2] = {r1, r3};
                #pragma unroll
                for (int mi = 0; mi < 2; mi++) {
                    mma16816(acc[mi][2*nj],   a[mi], b0);
                    mma16816(acc[mi][2*nj+1], a[mi], b1);
                }
            }
        }
    };

    #pragma unroll
    for (int s = 0; s < STAGES - 1; s++) {
        if (s < nc) load_stage(s, kbase + s * 64);
        CP_COMMIT();
    }
    int buf = 0, nxt = STAGES - 1;
    for (int c = 0; c < nc; c++) {
        CP_WAIT(STAGES - 2);
        __syncthreads();
        if (c + STAGES - 1 < nc) {
            load_stage(nxt, kbase + (c + STAGES - 1) * 64);
            CP_COMMIT();
        } else {
            CP_COMMIT();
        }
        compute(buf);
        if (++buf == STAGES) buf = 0;
        if (++nxt == STAGES) nxt = 0;
    }

    float* Cfo = Cf ? Cf + (long long)ks * slabStride : nullptr;
    const int rl = lane >> 2, cl = (lane & 3) * 2;
    #pragma unroll
    for (int mi = 0; mi < 2; mi++) {
        #pragma unroll
        for (int hf = 0; hf < 2; hf++) {
            const long long grow = bm0 + wm * 32 + mi * 16 + rl + hf * 8;
            float brow = 0.f;
            if (bias && (flags & 2)) brow = bias[grow];
            const long long base = bz * sC + grow * (long long)N + bn0 + wn * 64;
            #pragma unroll
            for (int nb = 0; nb < 8; nb++) {
                const int coff = nb * 8 + cl;
                float v0 = acc[mi][nb][hf*2+0] * alpha;
                float v1 = acc[mi][nb][hf*2+1] * alpha;
                if (bias) {
                    if (flags & 2) { v0 += brow; v1 += brow; }
                    else {
                        const long long gcol = bn0 + wn * 64 + coff;
                        v0 += bias[gcol]; v1 += bias[gcol + 1];
                    }
                }
                if (flags & 1) { v0 = fmaxf(v0, 0.f); v1 = fmaxf(v1, 0.f); }
                if (Cfo) *reinterpret_cast<float2*>(Cfo + base + coff) = make_float2(v0, v1);
                if (Ch) {
                    __half2 p = __floats2half2_rn(v0, v1);
                    *reinterpret_cast<uint32_t*>(Ch + base + coff) =
                        *reinterpret_cast<uint32_t*>(&p);
                }
            }
        }
    }
}

// ---------------- fp16 tensor GEMM 128x64 (narrow N) --------------------------
#define STAGE_BYTES64 24576   // A 16KB + B 8KB

__global__ void __launch_bounds__(256, 2)
mma_gemm64(const h16* __restrict__ A, const h16* __restrict__ B,
           const float* __restrict__ bias, float alpha, int flags,
           float* __restrict__ Cf, h16* __restrict__ Ch,
           int M, int N, int K, long long sA, long long sB, long long sC,
           int kspl, long long slabStride)
{
    extern __shared__ char sm[];
    const int tid = threadIdx.x, lane = tid & 31, wid = tid >> 5;
    const int wm = wid & 3, wn = wid >> 2;          // warp tile 32(m) x 32(n)
    const int zb = blockIdx.z;
    const long long bz = zb / kspl;
    const int ks = zb - (int)bz * kspl;
    const int Kc = K / kspl;
    const int bm0 = blockIdx.y << 7, bn0 = blockIdx.x << 6;

    const char* gA = (const char*)(A + bz * sA + (long long)bm0 * K);
    const char* gB = (const char*)(B + bz * sB + (long long)bn0 * K);
    const uint32_t sbase = u32smem(sm);
    const long long rowbytes = (long long)K * 2;

    float acc[2][4][4];
    #pragma unroll
    for (int i = 0; i < 2; i++)
        #pragma unroll
        for (int j = 0; j < 4; j++)
            #pragma unroll
            for (int q = 0; q < 4; q++) acc[i][j][q] = 0.f;

    const int nc = Kc >> 6;
    const int kbase = ks * Kc;

    auto load_stage = [&](int buf, int k0) {
        uint32_t sb = sbase + buf * STAGE_BYTES64;
        // A: 128 rows x 128B
        #pragma unroll
        for (int i = 0; i < 4; i++) {
            int idx = i * 256 + tid;
            int r = idx >> 3, c = idx & 7;
            uint32_t so = sb + r * 128 + ((c ^ (r & 7)) << 4);
            cpa16(so, gA + (long long)r * rowbytes + (long long)k0 * 2 + c * 16);
        }
        // B: 64 rows x 128B
        #pragma unroll
        for (int i = 0; i < 2; i++) {
            int idx = i * 256 + tid;
            int r = idx >> 3, c = idx & 7;
            uint32_t so = sb + 16384 + r * 128 + ((c ^ (r & 7)) << 4);
            cpa16(so, gB + (long long)r * rowbytes + (long long)k0 * 2 + c * 16);
        }
    };

    auto compute = [&](int buf) {
        uint32_t sbA = sbase + buf * STAGE_BYTES64;
        uint32_t sbB = sbA + 16384;
        #pragma unroll
        for (int s = 0; s < 4; s++) {
            uint32_t a[2][4];
            #pragma unroll
            for (int mi = 0; mi < 2; mi++) {
                int row = wm * 32 + mi * 16 + (lane & 15);
                int c = 2 * s + (lane >> 4);
                uint32_t off = row * 128 + ((c ^ (row & 7)) << 4);
                ldsm_x4(a[mi][0], a[mi][1], a[mi][2], a[mi][3], sbA + off);
            }
            #pragma unroll
            for (int nj = 0; nj < 2; nj++) {
                int row = wn * 32 + nj * 16 + (lane & 15);
                int c = 2 * s + (lane >> 4);
                uint32_t off = row * 128 + ((c ^ (row & 7)) << 4);
                uint32_t r0, r1, r2, r3;
                ldsm_x4(r0, r1, r2, r3, sbB + off);
                uint32_t b0[2] = {r0, r2}, b1[2] = {r1, r3};
                #pragma unroll
                for (int mi = 0; mi < 2; mi++) {
                    mma16816(acc[mi][2*nj],   a[mi], b0);
                    mma16816(acc[mi][2*nj+1], a[mi], b1);
                }
            }
        }
    };

    #pragma unroll
    for (int s = 0; s < STAGES - 1; s++) {
        if (s < nc) load_stage(s, kbase + s * 64);
        CP_COMMIT();
    }
    int buf = 0, nxt = STAGES - 1;
    for (int c = 0; c < nc; c++) {
        CP_WAIT(STAGES - 2);
        __syncthreads();
        if (c + STAGES - 1 < nc) {
            load_stage(nxt, kbase + (c + STAGES - 1) * 64);
            CP_COMMIT();
        } else {
            CP_COMMIT();
        }
        compute(buf);
        if (++buf == STAGES) buf = 0;
        if (++nxt == STAGES) nxt = 0;
    }

    float* Cfo = Cf ? Cf + (long long)ks * slabStride : nullptr;
    const int rl = lane >> 2, cl = (lane & 3) * 2;
    #pragma unroll
    for (int mi = 0; mi < 2; mi++) {
        #pragma unroll
        for (int hf = 0; hf < 2; hf++) {
            const long long grow = bm0 + wm * 32 + mi * 16 + rl + hf * 8;
            float brow = 0.f;
            if (bias && (flags & 2)) brow = bias[grow];
            const long long base = bz * sC + grow * (long long)N + bn0 + wn * 32;
            #pragma unroll
            for (int nb = 0; nb < 4; nb++) {
                const int coff = nb * 8 + cl;
                float v0 = acc[mi][nb][hf*2+0] * alpha;
                float v1 = acc[mi][nb][hf*2+1] * alpha;
                if (bias) {
                    if (flags & 2) { v0 += brow; v1 += brow; }
                    else {
                        const long long gcol = bn0 + wn * 32 + coff;
                        v0 += bias[gcol]; v1 += bias[gcol + 1];
                    }
                }
                if (flags & 1) { v0 = fmaxf(v0, 0.f); v1 = fmaxf(v1, 0.f); }
                if (Cfo) *reinterpret_cast<float2*>(Cfo + base + coff) = make_float2(v0, v1);
                if (Ch) {
                    __half2 p = __floats2half2_rn(v0, v1);
                    *reinterpret_cast<uint32_t*>(Ch + base + coff) =
                        *reinterpret_cast<uint32_t*>(&p);
                }
            }
        }
    }
}

// ---------------- fp32 -> fp16 ----------------
__global__ void cvt16(const float* __restrict__ in, h16* __restrict__ out, long long n4)
{
    long long i = blockIdx.x * (long long)blockDim.x + threadIdx.x;
    if (i >= n4) return;
    float4 v = reinterpret_cast<const float4*>(in)[i];
    __half2 a = __floats2half2_rn(v.x, v.y);
    __half2 b = __floats2half2_rn(v.z, v.w);
    reinterpret_cast<uint2*>(out)[i] = make_uint2(*(uint32_t*)&a, *(uint32_t*)&b);
}

// ---------------- sum ns fp32 slabs -> fp16 ----------------
__global__ void reduce16(const float* __restrict__ slabs, long long sstride4,
                         int ns, h16* __restrict__ out, long long n4)
{
    long long i = blockIdx.x * (long long)blockDim.x + threadIdx.x;
    if (i >= n4) return;
    const float4* p = reinterpret_cast<const float4*>(slabs);
    float4 v = p[i];
    for (int s = 1; s < ns; s++) {
        float4 t = p[i + s * sstride4];
        v.x += t.x; v.y += t.y; v.z += t.z; v.w += t.w;
    }
    __half2 a = __floats2half2_rn(v.x, v.y);
    __half2 b = __floats2half2_rn(v.z, v.w);
    reinterpret_cast<uint2*>(out)[i] = make_uint2(*(uint32_t*)&a, *(uint32_t*)&b);
}

// ---------------- transpose: [batch,R,C] f32 -> [batch,C,R] fp16 -------------
__global__ void transpose16(const float* __restrict__ in, h16* __restrict__ out,
                            int R, int C)
{
    __shared__ float tile[32][33];
    const long long b = blockIdx.z;
    const int c0 = blockIdx.x << 5;
    const int r0 = blockIdx.y << 5;
    const float* ib = in + b * (long long)R * C;
    const int tx = threadIdx.x, ty = threadIdx.y;
    #pragma unroll
    for (int i = 0; i < 4; i++)
        tile[ty + 8*i][tx] = ib[(long long)(r0 + ty + 8*i) * C + c0 + tx];
    __syncthreads();
    h16* ob = out + b * (long long)R * C;
    #pragma unroll
    for (int i = 0; i < 4; i++) {
        float v = tile[tx][ty + 8*i];
        ob[(long long)(c0 + ty + 8*i) * R + r0 + tx] = __float2half_rn(v);
    }
}

// ---------------- batched bias-fold vectors (all layers) ----------------
__global__ void pvec_all(const float* __restrict__ Wk, const float* __restrict__ bq,
                         float* __restrict__ pvec)
{
    int l = blockIdx.x, dk = threadIdx.x;
    const float* Wkl = Wk + (long long)l * D_ * DK;
    const float* bql = bq + (long long)l * D_;
    float s = 0.f;
    for (int e = 0; e < D_; e++) s += bql[e] * Wkl[(long long)e * DK + dk];
    pvec[l * DK + dk] = s;
}
__global__ void wvec_all(const float* __restrict__ mem, const float* __restrict__ pvec,
                         float* __restrict__ w, float scale)
{
    const int per = BN * T1 / 256;
    int l = blockIdx.x / per;
    int i = (blockIdx.x - l * per) * 256 + threadIdx.x;
    const float* m = mem + (long long)i * DK;
    const float* pv = pvec + l * DK;
    float s = 0.f;
    #pragma unroll 8
    for (int dk = 0; dk < DK; dk++) s += m[dk] * pv[dk];
    w[(long long)l * BN * T1 + i] = s * scale;
}

// ---------------- reductions ----------------
__device__ __forceinline__ float warpMax(float v) {
    #pragma unroll
    for (int o = 16; o > 0; o >>= 1) v = fmaxf(v, __shfl_xor_sync(0xffffffffu, v, o));
    return v;
}
__device__ __forceinline__ float warpSum(float v) {
    #pragma unroll
    for (int o = 16; o > 0; o >>= 1) v += __shfl_xor_sync(0xffffffffu, v, o);
    return v;
}
__device__ __forceinline__ float blockMax(float v) {
    __shared__ float sh[8];
    v = warpMax(v);
    __syncthreads();
    if ((threadIdx.x & 31) == 0) sh[threadIdx.x >> 5] = v;
    __syncthreads();
    float r = -1e30f;
    int nw = blockDim.x >> 5;
    #pragma unroll
    for (int i = 0; i < 8; i++) if (i < nw) r = fmaxf(r, sh[i]);
    return r;
}
__device__ __forceinline__ float blockSum(float v) {
    __shared__ float sh[8];
    v = warpSum(v);
    __syncthreads();
    if ((threadIdx.x & 31) == 0) sh[threadIdx.x >> 5] = v;
    __syncthreads();
    float r = 0.0f;
    int nw = blockDim.x >> 5;
    #pragma unroll
    for (int i = 0; i < 8; i++) if (i < nw) r += sh[i];
    return r;
}

// ---------------- dual softmax + blend -> fp16 ----------------
__global__ void __launch_bounds__(256)
softmax_blend(const float* __restrict__ mixed, const float* __restrict__ att,
              const float* __restrict__ w, h16* __restrict__ out)
{
    const long long base = (long long)blockIdx.x * T1;
    const int b = blockIdx.x >> 10;
    const int tid = threadIdx.x;
    float mv[8], av[8];
    float m1 = -1e30f, m2 = -1e30f;
    #pragma unroll
    for (int i = 0; i < 8; i++) {
        int c = tid + i * 256;
        mv[i] = mixed[base + c];
        av[i] = att[base + c] + w[(long long)b * T1 + c];
        m1 = fmaxf(m1, mv[i]);
        m2 = fmaxf(m2, av[i]);
    }
    m1 = blockMax(m1);
    m2 = blockMax(m2);
    float s1 = 0.f, s2 = 0.f;
    #pragma unroll
    for (int i = 0; i < 8; i++) {
        mv[i] = __expf(mv[i] - m1);
        av[i] = __expf(av[i] - m2);
        s1 += mv[i]; s2 += av[i];
    }
    s1 = blockSum(s1);
    s2 = blockSum(s2);
    const float r1 = TTMIX / s1, r2 = (1.0f - TTMIX) / s2;
    #pragma unroll
    for (int i = 0; i < 8; i++) {
        int c = tid + i * 256;
        out[base + c] = __float2half_rn(mv[i] * r1 + av[i] * r2);
    }
}

// ---------------- residual add + LayerNorm -> fp32 + fp16 --------------------
__global__ void __launch_bounds__(128)
add_ln(float* __restrict__ x, const float* __restrict__ slabs, int ns,
       long long sstride, const float* __restrict__ bias2,
       const float* __restrict__ g, const float* __restrict__ b,
       h16* __restrict__ xh)
{
    const long long base = (long long)blockIdx.x * D_;
    const int tid = threadIdx.x;
    float v[3];
    #pragma unroll
    for (int i = 0; i < 3; i++) {
        int c = tid + i * 128;
        float t = x[base + c];
        for (int s = 0; s < ns; s++) t += slabs[s * sstride + base + c];
        if (bias2) t += bias2[c];
        v[i] = t;
    }
    float s = v[0] + v[1] + v[2];
    s = blockSum(s);
    const float mean = s * (1.0f / D_);
    float q = 0.f;
    #pragma unroll
    for (int i = 0; i < 3; i++) { float d = v[i] - mean; q += d * d; }
    q = blockSum(q);
    const float rstd = rsqrtf(q * (1.0f / D_) + LN_EPS);
    #pragma unroll
    for (int i = 0; i < 3; i++) {
        int c = tid + i * 128;
        float o = (v[i] - mean) * rstd * g[c] + b[c];
        x[base + c] = o;
        xh[base + c] = __float2half_rn(o);
    }
}

// ---------------- host ----------------
#define SMEM_DYN   (STAGES * STAGE_BYTES)
#define SMEM_DYN64 (STAGES * STAGE_BYTES64)
#define SYM(p, s) do { void* _t; cudaGetSymbolAddress(&_t, s); p = (decltype(p))_t; } while (0)

static void split(const float* in, h16* out, long long n, cudaStream_t st) {
    long long n4 = n / 4;
    cvt16<<<(unsigned)((n4 + 255) / 256), 256, 0, st>>>(in, out, n4);
}
static void gemm(const h16* A, const h16* B, const float* bias, float alpha,
                 int flags, float* Cf, h16* Ch,
                 int M, int N, int K, int batch,
                 long long sA, long long sB, long long sC, cudaStream_t st,
                 int kspl = 1, long long slabStride = 0) {
    dim3 g(N / 128, M / 128, batch * kspl);
    mma_gemm<<<g, 256, SMEM_DYN, st>>>(A, B, bias, alpha, flags, Cf, Ch,
                                       M, N, K, sA, sB, sC, kspl, slabStride);
}
static void gemm64(const h16* A, const h16* B, const float* bias, float alpha,
                   int flags, float* Cf, h16* Ch,
                   int M, int N, int K, int batch,
                   long long sA, long long sB, long long sC, cudaStream_t st,
                   int kspl = 1, long long slabStride = 0) {
    dim3 g(N / 64, M / 128, batch * kspl);
    mma_gemm64<<<g, 256, SMEM_DYN64, st>>>(A, B, bias, alpha, flags, Cf, Ch,
                                           M, N, K, sA, sB, sC, kspl, slabStride);
}
static void transpose_split(const float* in, h16* out, int R, int C, int batch,
                            cudaStream_t st) {
    dim3 g(C / 32, R / 32, batch), b(32, 8);
    transpose16<<<g, b, 0, st>>>(in, out, R, C);
}

extern "C" void kernel_launch(void* const* d_in, const int* in_sizes, int n_in,
                              void* d_out, int out_size)
{
    (void)in_sizes; (void)n_in; (void)out_size;
    const float* tgt     = (const float*)d_in[0];
    const float* memory  = (const float*)d_in[1];
    const float* score_c = (const float*)d_in[2];
    const float* out_c   = (const float*)d_in[3];
    const float* Wq  = (const float*)d_in[4];
    const float* bq  = (const float*)d_in[5];
    const float* Wk  = (const float*)d_in[6];
    const float* Wv  = (const float*)d_in[8];
    const float* bv  = (const float*)d_in[9];
    const float* Wkn = (const float*)d_in[10];
    const float* bkn = (const float*)d_in[11];
    const float* Wun = (const float*)d_in[12];
    const float* bun = (const float*)d_in[13];
    const float* W1  = (const float*)d_in[14];
    const float* b1  = (const float*)d_in[15];
    const float* W2  = (const float*)d_in[16];
    const float* b2  = (const float*)d_in[17];
    const float* g1  = (const float*)d_in[18];
    const float* be1 = (const float*)d_in[19];
    const float* g2  = (const float*)d_in[20];
    const float* be2 = (const float*)d_in[21];

    float *x, *att, *mix, *m2slab, *z1slab, *y2slab, *zslab, *pvec, *wvec;
    SYM(x, g_x); SYM(att, g_att); SYM(mix, g_mix);
    SYM(m2slab, g_m2slab); SYM(z1slab, g_z1slab);
    SYM(y2slab, g_y2slab); SYM(zslab, g_zslab);
    SYM(pvec, g_pvec); SYM(wvec, g_wvec);
    h16 *xh,*qxh,*mh,*mth,*unh,*knh,*m2h,*blh,*hh,*oh,*sth;
    h16 *wqth,*wkth,*wqkth,*wvh,*wnh,*wuh,*w1h,*w2h;
    SYM(xh,g_xh); SYM(qxh,g_qxh); SYM(mh,g_mh); SYM(mth,g_mth);
    SYM(unh,g_unh); SYM(knh,g_knh); SYM(m2h,g_m2h); SYM(blh,g_blh);
    SYM(hh,g_hh); SYM(oh,g_oh); SYM(sth,g_sth);
    SYM(wqth,g_wqth); SYM(wkth,g_wkth); SYM(wqkth,g_wqkth);
    SYM(wvh,g_wvh); SYM(wnh,g_wnh); SYM(wuh,g_wuh);
    SYM(w1h,g_w1h); SYM(w2h,g_w2h);

    cudaFuncSetAttribute(mma_gemm, cudaFuncAttributeMaxDynamicSharedMemorySize, SMEM_DYN);
    cudaFuncSetAttribute(mma_gemm64, cudaFuncAttributeMaxDynamicSharedMemorySize, SMEM_DYN64);

    // ---- streams/events (created once) ----
    static cudaStream_t s1 = nullptr, s2 = nullptr;
    static cudaEvent_t e0 = nullptr, s1done = nullptr;
    static cudaEvent_t ev_m2t[LY], ev_att[LY], ev_x[LY];
    if (!s1) {
        cudaStreamCreateWithFlags(&s1, cudaStreamNonBlocking);
        cudaStreamCreateWithFlags(&s2, cudaStreamNonBlocking);
        cudaEventCreateWithFlags(&e0, cudaEventDisableTiming);
        cudaEventCreateWithFlags(&s1done, cudaEventDisableTiming);
        for (int l = 0; l < LY; l++) {
            cudaEventCreateWithFlags(&ev_m2t[l], cudaEventDisableTiming);
            cudaEventCreateWithFlags(&ev_att[l], cudaEventDisableTiming);
            cudaEventCreateWithFlags(&ev_x[l], cudaEventDisableTiming);
        }
    }

    const float scale = 1.0f / sqrtf((float)D_);
    cudaStream_t s0 = 0;

    // ---- prologue (r12 structure) ----
    cudaMemcpyAsync(x, tgt, (size_t)NX * 4, cudaMemcpyDeviceToDevice, s0);
    split(tgt, xh, NX, s0);
    split(memory, mh, NMEM, s0);
    split(out_c, oh, NOC, s0);
    split(Wv, wvh, NWKT, s0);
    split(Wkn, wnh, NWQT, s0);
    split(Wun, wuh, NWQT, s0);
    split(W1, w1h, NW1, s0);
    split(W2, w2h, NW1, s0);
    transpose_split(memory, mth, T1, DK, BN, s0);
    transpose_split(Wq, wqth, D_, D_, LY, s0);
    transpose_split(Wk, wkth, D_, DK, LY, s0);
    gemm(wkth, wqth, nullptr, 1.f, 0, nullptr, wqkth,
         DK, D_, D_, LY, (long long)DK*D_, (long long)D_*D_, (long long)DK*D_, s0);
    pvec_all<<<LY, DK, 0, s0>>>(Wk, bq, pvec);
    wvec_all<<<LY * (BN*T1/256), 256, 0, s0>>>(memory, pvec, wvec, scale);
    cudaEventRecord(e0, s0);

    // ---- stream s1: x-independent precompute (all layers; gated on e0) ----
    cudaStreamWaitEvent(s1, e0, 0);
    for (int l = 0; l < LY; l++) {
        const long long oq = (long long)l * D_ * D_;
        gemm(wnh + oq, oh + (long long)l*BN*TC*D_, bkn + (long long)l*D_, 1.f, 2,
             nullptr, knh, D_, TC, D_, BN, 0, (long long)TC*D_, (long long)D_*TC, s1);
        transpose_split(score_c + (long long)l*BN*TC*T1, sth, TC, T1, BN, s1);
        gemm(sth, knh, nullptr, scale, 0, m2slab, nullptr,
             T1, D_, TC, BN, (long long)T1*TC, (long long)D_*TC, (long long)T1*D_,
             s1, 2, (long long)NM2);
        reduce16<<<(NM2/4 + 255)/256, 256, 0, s1>>>(
            m2slab, NM2/4, 2, m2h + (long long)l*NM2, NM2/4);
        cudaEventRecord(ev_m2t[l], s1);
    }
    cudaEventRecord(s1done, s1);

    // ---- main + s2 per-layer ----
    for (int l = 0; l < LY; l++) {
        const long long oq = (long long)l * D_ * D_;
        const long long ok = (long long)l * D_ * DK;
        const long long o1 = (long long)l * FF * D_;

        // s2: qx -> att (qx via narrow-N tile: 64 -> 128 CTAs)
        cudaStreamWaitEvent(s2, (l == 0) ? e0 : ev_x[l], 0);
        gemm64(xh, wqkth + ok, nullptr, 1.f, 0, nullptr, qxh,
               BN*T_, DK, D_, 1, 0, 0, 0, s2);
        gemm(qxh, mh, nullptr, scale, 0, att, nullptr,
             T_, T1, DK, BN, (long long)T_*DK, (long long)T1*DK, (long long)T_*T1, s2);
        cudaEventRecord(ev_att[l], s2);

        // main: unk (narrow-N: 96 -> 192 CTAs)
        gemm64(xh, wuh + oq, bun + (long long)l*D_, 1.f, 0, nullptr, unh,
               BN*T_, D_, D_, 1, 0, 0, 0, s0);
        // main: mixed (needs M2T[l])
        cudaStreamWaitEvent(s0, ev_m2t[l], 0);
        gemm(unh, m2h + (long long)l*NM2, nullptr, 1.f, 0, mix, nullptr,
             T_, T1, D_, BN, (long long)T_*D_, (long long)T1*D_, (long long)T_*T1, s0);
        // main: softmax blend (needs att)
        cudaStreamWaitEvent(s0, ev_att[l], 0);
        softmax_blend<<<BN*T_, 256, 0, s0>>>(mix, att, wvec + (long long)l*BN*T1, blh);
        // z1 = blended @ memT^T, split-K=4
        gemm(blh, mth, nullptr, 1.f, 0, z1slab, nullptr,
             T_, DK, T1, BN, (long long)T_*T1, (long long)DK*T1, (long long)T_*DK,
             s0, 4, (long long)NQX);
        reduce16<<<(NQX/4 + 255)/256, 256, 0, s0>>>(z1slab, NQX/4, 4, qxh, NQX/4);
        // z = z1 @ Wv^T, split-K=2, narrow-N (192 -> 384 CTAs)
        gemm64(qxh, wvh + ok, nullptr, 1.f, 0, zslab, nullptr,
               BN*T_, D_, DK, 1, 0, 0, 0, s0, 2, (long long)NX);
        add_ln<<<BN*T_, 128, 0, s0>>>(x, zslab, 2, (long long)NX, bv + (long long)l*D_,
                                      g1 + (long long)l*D_, be1 + (long long)l*D_, xh);
        // h = relu(x @ W1^T + b1)
        gemm(xh, w1h + o1, b1 + (long long)l*FF, 1.f, 1, nullptr, hh,
             BN*T_, FF, D_, 1, 0, 0, 0, s0);
        // y2 = h @ W2^T, split-K=3, narrow-N (288 -> 576 CTAs)
        gemm64(hh, w2h + o1, nullptr, 1.f, 0, y2slab, nullptr,
               BN*T_, D_, FF, 1, 0, 0, 0, s0, 3, (long long)NX);
        add_ln<<<BN*T_, 128, 0, s0>>>(x, y2slab, 3, (long long)NX, b2 + (long long)l*D_,
                                      g2 + (long long)l*D_, be2 + (long long)l*D_, xh);
        if (l + 1 < LY) cudaEventRecord(ev_x[l + 1], s0);
    }

    cudaStreamWaitEvent(s0, s1done, 0);
    cudaMemcpyAsync(d_out, x, (size_t)NX * 4, cudaMemcpyDeviceToDevice, s0);
}

// round 15
// speedup vs baseline: 1.0159x; 1.0134x over previous
#include <cuda_runtime.h>
#include <cuda_fp16.h>
#include <math.h>
#include <stdint.h>

typedef __half h16;

// ---------------- problem dims ----------------
#define LY 4
#define BN 4
#define T_ 1024
#define TC 1024
#define T1 2048
#define D_ 384
#define DK 256
#define FF 1536
#define TTMIX 0.1f
#define LN_EPS 1e-5f

#define NX   (BN*T_*D_)
#define NAT  (BN*T_*T1)
#define NQX  (BN*T_*DK)
#define NH_  (BN*T_*FF)
#define NMEM (BN*T1*DK)
#define NOC  (LY*BN*TC*D_)
#define NSCT (BN*T1*TC)
#define NM2  (BN*T1*D_)
#define NWQT (LY*D_*D_)
#define NWKT (LY*D_*DK)
#define NW1  (LY*FF*D_)

// ---------------- scratch ----------------
__device__ __align__(128) float g_x[NX], g_att[NAT], g_mix[NAT];
__device__ __align__(128) float g_m2slab[2*NM2];
__device__ __align__(128) float g_y2slab[3*NX], g_zslab[4*NX];
__device__ __align__(128) float g_pvec[LY*DK], g_wvec[LY*BN*T1];
__device__ __align__(128) h16 g_xh[NX], g_qxh[NQX];
__device__ __align__(128) h16 g_mh[NMEM];
__device__ __align__(128) h16 g_unh[NX], g_knh[NX];
__device__ __align__(128) h16 g_m2h[LY*NM2];
__device__ __align__(128) h16 g_vth[NM2];
__device__ __align__(128) h16 g_blh[NAT];
__device__ __align__(128) h16 g_hh[NH_];
__device__ __align__(128) h16 g_oh[NOC], g_sth[NSCT];
__device__ __align__(128) h16 g_wqth[NWQT], g_wkth[NWKT], g_wqkth[NWKT];
__device__ __align__(128) h16 g_wvh[NWKT], g_wnh[NWQT], g_wuh[NWQT];
__device__ __align__(128) h16 g_w1h[NW1], g_w2h[NW1];

// ---------------- helpers ----------------
__device__ __forceinline__ uint32_t u32smem(const void* p) {
    uint32_t a;
    asm("{ .reg .u64 t; cvta.to.shared.u64 t, %1; cvt.u32.u64 %0, t; }" : "=r"(a) : "l"(p));
    return a;
}
__device__ __forceinline__ void cpa16(uint32_t s, const void* g) {
    asm volatile("cp.async.cg.shared.global [%0], [%1], 16;" :: "r"(s), "l"(g));
}
#define CP_COMMIT() asm volatile("cp.async.commit_group;" ::: "memory")
#define CP_WAIT(n)  asm volatile("cp.async.wait_group %0;" :: "n"(n) : "memory")

__device__ __forceinline__ void ldsm_x4(uint32_t& r0, uint32_t& r1, uint32_t& r2,
                                        uint32_t& r3, uint32_t a) {
    asm volatile("ldmatrix.sync.aligned.m8n8.x4.shared.b16 {%0,%1,%2,%3}, [%4];"
                 : "=r"(r0), "=r"(r1), "=r"(r2), "=r"(r3) : "r"(a));
}
__device__ __forceinline__ void mma16816(float* d, const uint32_t* a, const uint32_t* b) {
    asm volatile(
        "mma.sync.aligned.m16n8k16.row.col.f32.f16.f16.f32 "
        "{%0,%1,%2,%3},{%4,%5,%6,%7},{%8,%9},{%0,%1,%2,%3};"
        : "+f"(d[0]), "+f"(d[1]), "+f"(d[2]), "+f"(d[3])
        : "r"(a[0]), "r"(a[1]), "r"(a[2]), "r"(a[3]), "r"(b[0]), "r"(b[1]));
}

// ---------------- fp16 tensor GEMM: C = alpha*A@B^T (+bias)(+relu) -----------
#define STAGES 3
#define STAGE_BYTES 32768

__global__ void __launch_bounds__(256, 2)
mma_gemm(const h16* __restrict__ A, const h16* __restrict__ B,
         const float* __restrict__ bias, float alpha, int flags,
         float* __restrict__ Cf, h16* __restrict__ Ch,
         int M, int N, int K, long long sA, long long sB, long long sC,
         int kspl, long long slabStride)
{
    extern __shared__ char sm[];
    const int tid = threadIdx.x, lane = tid & 31, wid = tid >> 5;
    const int wm = wid & 3, wn = wid >> 2;
    const int zb = blockIdx.z;
    const long long bz = zb / kspl;
    const int ks = zb - (int)bz * kspl;
    const int Kc = K / kspl;
    const int bm0 = blockIdx.y << 7, bn0 = blockIdx.x << 7;

    const char* gsrc[2] = {
        (const char*)(A + bz * sA + (long long)bm0 * K),
        (const char*)(B + bz * sB + (long long)bn0 * K) };
    const uint32_t sbase = u32smem(sm);
    const long long rowbytes = (long long)K * 2;

    float acc[2][8][4];
    #pragma unroll
    for (int i = 0; i < 2; i++)
        #pragma unroll
        for (int j = 0; j < 8; j++)
            #pragma unroll
            for (int q = 0; q < 4; q++) acc[i][j][q] = 0.f;

    const int nc = Kc >> 6;
    const int kbase = ks * Kc;

    auto load_stage = [&](int buf, int k0) {
        uint32_t sb = sbase + buf * STAGE_BYTES;
        #pragma unroll
        for (int t = 0; t < 2; t++) {
            uint32_t ab = sb + t * 16384;
            const char* g = gsrc[t];
            #pragma unroll
            for (int i = 0; i < 4; i++) {
                int idx = i * 256 + tid;
                int r = idx >> 3, c = idx & 7;
                uint32_t so = ab + r * 128 + ((c ^ (r & 7)) << 4);
                cpa16(so, g + (long long)r * rowbytes + (long long)k0 * 2 + c * 16);
            }
        }
    };

    auto compute = [&](int buf) {
        uint32_t sbA = sbase + buf * STAGE_BYTES;
        uint32_t sbB = sbA + 16384;
        #pragma unroll
        for (int s = 0; s < 4; s++) {
            uint32_t a[2][4];
            #pragma unroll
            for (int mi = 0; mi < 2; mi++) {
                int row = wm * 32 + mi * 16 + (lane & 15);
                int c = 2 * s + (lane >> 4);
                uint32_t off = row * 128 + ((c ^ (row & 7)) << 4);
                ldsm_x4(a[mi][0], a[mi][1], a[mi][2], a[mi][3], sbA + off);
            }
            #pragma unroll
            for (int nj = 0; nj < 4; nj++) {
                int row = wn * 64 + nj * 16 + (lane & 15);
                int c = 2 * s + (lane >> 4);
                uint32_t off = row * 128 + ((c ^ (row & 7)) << 4);
                uint32_t r0, r1, r2, r3;
                ldsm_x4(r0, r1, r2, r3, sbB + off);
                uint32_t b0[2] = {r0, r2}, b1[2] = {r1, r3};
                #pragma unroll
                for (int mi = 0; mi < 2; mi++) {
                    mma16816(acc[mi][2*nj],   a[mi], b0);
                    mma16816(acc[mi][2*nj+1], a[mi], b1);
                }
            }
        }
    };

    #pragma unroll
    for (int s = 0; s < STAGES - 1; s++) {
        if (s < nc) load_stage(s, kbase + s * 64);
        CP_COMMIT();
    }
    int buf = 0, nxt = STAGES - 1;
    for (int c = 0; c < nc; c++) {
        CP_WAIT(STAGES - 2);
        __syncthreads();
        if (c + STAGES - 1 < nc) {
            load_stage(nxt, kbase + (c + STAGES - 1) * 64);
            CP_COMMIT();
        } else {
            CP_COMMIT();
        }
        compute(buf);
        if (++buf == STAGES) buf = 0;
        if (++nxt == STAGES) nxt = 0;
    }

    float* Cfo = Cf ? Cf + (long long)ks * slabStride : nullptr;
    const int rl = lane >> 2, cl = (lane & 3) * 2;
    #pragma unroll
    for (int mi = 0; mi < 2; mi++) {
        #pragma unroll
        for (int hf = 0; hf < 2; hf++) {
            const long long grow = bm0 + wm * 32 + mi * 16 + rl + hf * 8;
            float brow = 0.f;
            if (bias && (flags & 2)) brow = bias[grow];
            const long long base = bz * sC + grow * (long long)N + bn0 + wn * 64;
            #pragma unroll
            for (int nb = 0; nb < 8; nb++) {
                const int coff = nb * 8 + cl;
                float v0 = acc[mi][nb][hf*2+0] * alpha;
                float v1 = acc[mi][nb][hf*2+1] * alpha;
                if (bias) {
                    if (flags & 2) { v0 += brow; v1 += brow; }
                    else {
                        const long long gcol = bn0 + wn * 64 + coff;
                        v0 += bias[gcol]; v1 += bias[gcol + 1];
                    }
                }
                if (flags & 1) { v0 = fmaxf(v0, 0.f); v1 = fmaxf(v1, 0.f); }
                if (Cfo) *reinterpret_cast<float2*>(Cfo + base + coff) = make_float2(v0, v1);
                if (Ch) {
                    __half2 p = __floats2half2_rn(v0, v1);
                    *reinterpret_cast<uint32_t*>(Ch + base + coff) =
                        *reinterpret_cast<uint32_t*>(&p);
                }
            }
        }
    }
}

// ---------------- fp32 -> fp16 ----------------
__global__ void cvt16(const float* __restrict__ in, h16* __restrict__ out, long long n4)
{
    long long i = blockIdx.x * (long long)blockDim.x + threadIdx.x;
    if (i >= n4) return;
    float4 v = reinterpret_cast<const float4*>(in)[i];
    __half2 a = __floats2half2_rn(v.x, v.y);
    __half2 b = __floats2half2_rn(v.z, v.w);
    reinterpret_cast<uint2*>(out)[i] = make_uint2(*(uint32_t*)&a, *(uint32_t*)&b);
}

// ---------------- sum ns fp32 slabs -> fp16 ----------------
__global__ void reduce16(const float* __restrict__ slabs, long long sstride4,
                         int ns, h16* __restrict__ out, long long n4)
{
    long long i = blockIdx.x * (long long)blockDim.x + threadIdx.x;
    if (i >= n4) return;
    const float4* p = reinterpret_cast<const float4*>(slabs);
    float4 v = p[i];
    for (int s = 1; s < ns; s++) {
        float4 t = p[i + s * sstride4];
        v.x += t.x; v.y += t.y; v.z += t.z; v.w += t.w;
    }
    __half2 a = __floats2half2_rn(v.x, v.y);
    __half2 b = __floats2half2_rn(v.z, v.w);
    reinterpret_cast<uint2*>(out)[i] = make_uint2(*(uint32_t*)&a, *(uint32_t*)&b);
}

// ---------------- transpose: [batch,R,C] f32 -> [batch,C,R] fp16 -------------
__global__ void transpose16(const float* __restrict__ in, h16* __restrict__ out,
                            int R, int C)
{
    __shared__ float tile[32][33];
    const long long b = blockIdx.z;
    const int c0 = blockIdx.x << 5;
    const int r0 = blockIdx.y << 5;
    const float* ib = in + b * (long long)R * C;
    const int tx = threadIdx.x, ty = threadIdx.y;
    #pragma unroll
    for (int i = 0; i < 4; i++)
        tile[ty + 8*i][tx] = ib[(long long)(r0 + ty + 8*i) * C + c0 + tx];
    __syncthreads();
    h16* ob = out + b * (long long)R * C;
    #pragma unroll
    for (int i = 0; i < 4; i++) {
        float v = tile[tx][ty + 8*i];
        ob[(long long)(c0 + ty + 8*i) * R + r0 + tx] = __float2half_rn(v);
    }
}

// ---------------- batched bias-fold vectors (all layers) ----------------
__global__ void pvec_all(const float* __restrict__ Wk, const float* __restrict__ bq,
                         float* __restrict__ pvec)
{
    int l = blockIdx.x, dk = threadIdx.x;
    const float* Wkl = Wk + (long long)l * D_ * DK;
    const float* bql = bq + (long long)l * D_;
    float s = 0.f;
    for (int e = 0; e < D_; e++) s += bql[e] * Wkl[(long long)e * DK + dk];
    pvec[l * DK + dk] = s;
}
__global__ void wvec_all(const float* __restrict__ mem, const float* __restrict__ pvec,
                         float* __restrict__ w, float scale)
{
    const int per = BN * T1 / 256;
    int l = blockIdx.x / per;
    int i = (blockIdx.x - l * per) * 256 + threadIdx.x;
    const float* m = mem + (long long)i * DK;
    const float* pv = pvec + l * DK;
    float s = 0.f;
    #pragma unroll 8
    for (int dk = 0; dk < DK; dk++) s += m[dk] * pv[dk];
    w[(long long)l * BN * T1 + i] = s * scale;
}

// ---------------- reductions ----------------
__device__ __forceinline__ float warpMax(float v) {
    #pragma unroll
    for (int o = 16; o > 0; o >>= 1) v = fmaxf(v, __shfl_xor_sync(0xffffffffu, v, o));
    return v;
}
__device__ __forceinline__ float warpSum(float v) {
    #pragma unroll
    for (int o = 16; o > 0; o >>= 1) v += __shfl_xor_sync(0xffffffffu, v, o);
    return v;
}
__device__ __forceinline__ float blockMax(float v) {
    __shared__ float sh[8];
    v = warpMax(v);
    __syncthreads();
    if ((threadIdx.x & 31) == 0) sh[threadIdx.x >> 5] = v;
    __syncthreads();
    float r = -1e30f;
    int nw = blockDim.x >> 5;
    #pragma unroll
    for (int i = 0; i < 8; i++) if (i < nw) r = fmaxf(r, sh[i]);
    return r;
}
__device__ __forceinline__ float blockSum(float v) {
    __shared__ float sh[8];
    v = warpSum(v);
    __syncthreads();
    if ((threadIdx.x & 31) == 0) sh[threadIdx.x >> 5] = v;
    __syncthreads();
    float r = 0.0f;
    int nw = blockDim.x >> 5;
    #pragma unroll
    for (int i = 0; i < 8; i++) if (i < nw) r += sh[i];
    return r;
}

// ---------------- dual softmax + blend -> fp16 ----------------
__global__ void __launch_bounds__(256)
softmax_blend(const float* __restrict__ mixed, const float* __restrict__ att,
              const float* __restrict__ w, h16* __restrict__ out)
{
    const long long base = (long long)blockIdx.x * T1;
    const int b = blockIdx.x >> 10;
    const int tid = threadIdx.x;
    float mv[8], av[8];
    float m1 = -1e30f, m2 = -1e30f;
    #pragma unroll
    for (int i = 0; i < 8; i++) {
        int c = tid + i * 256;
        mv[i] = mixed[base + c];
        av[i] = att[base + c] + w[(long long)b * T1 + c];
        m1 = fmaxf(m1, mv[i]);
        m2 = fmaxf(m2, av[i]);
    }
    m1 = blockMax(m1);
    m2 = blockMax(m2);
    float s1 = 0.f, s2 = 0.f;
    #pragma unroll
    for (int i = 0; i < 8; i++) {
        mv[i] = __expf(mv[i] - m1);
        av[i] = __expf(av[i] - m2);
        s1 += mv[i]; s2 += av[i];
    }
    s1 = blockSum(s1);
    s2 = blockSum(s2);
    const float r1 = TTMIX / s1, r2 = (1.0f - TTMIX) / s2;
    #pragma unroll
    for (int i = 0; i < 8; i++) {
        int c = tid + i * 256;
        out[base + c] = __float2half_rn(mv[i] * r1 + av[i] * r2);
    }
}

// ---------------- residual add + LayerNorm -> fp32 + fp16 --------------------
__global__ void __launch_bounds__(128)
add_ln(float* __restrict__ x, const float* __restrict__ slabs, int ns,
       long long sstride, const float* __restrict__ bias2,
       const float* __restrict__ g, const float* __restrict__ b,
       h16* __restrict__ xh)
{
    const long long base = (long long)blockIdx.x * D_;
    const int tid = threadIdx.x;
    float v[3];
    #pragma unroll
    for (int i = 0; i < 3; i++) {
        int c = tid + i * 128;
        float t = x[base + c];
        for (int s = 0; s < ns; s++) t += slabs[s * sstride + base + c];
        if (bias2) t += bias2[c];
        v[i] = t;
    }
    float s = v[0] + v[1] + v[2];
    s = blockSum(s);
    const float mean = s * (1.0f / D_);
    float q = 0.f;
    #pragma unroll
    for (int i = 0; i < 3; i++) { float d = v[i] - mean; q += d * d; }
    q = blockSum(q);
    const float rstd = rsqrtf(q * (1.0f / D_) + LN_EPS);
    #pragma unroll
    for (int i = 0; i < 3; i++) {
        int c = tid + i * 128;
        float o = (v[i] - mean) * rstd * g[c] + b[c];
        x[base + c] = o;
        xh[base + c] = __float2half_rn(o);
    }
}

// ---------------- host ----------------
#define SMEM_DYN (STAGES * STAGE_BYTES)
#define SYM(p, s) do { void* _t; cudaGetSymbolAddress(&_t, s); p = (decltype(p))_t; } while (0)

static void split(const float* in, h16* out, long long n, cudaStream_t st) {
    long long n4 = n / 4;
    cvt16<<<(unsigned)((n4 + 255) / 256), 256, 0, st>>>(in, out, n4);
}
static void gemm(const h16* A, const h16* B, const float* bias, float alpha,
                 int flags, float* Cf, h16* Ch,
                 int M, int N, int K, int batch,
                 long long sA, long long sB, long long sC, cudaStream_t st,
                 int kspl = 1, long long slabStride = 0) {
    dim3 g(N / 128, M / 128, batch * kspl);
    mma_gemm<<<g, 256, SMEM_DYN, st>>>(A, B, bias, alpha, flags, Cf, Ch,
                                       M, N, K, sA, sB, sC, kspl, slabStride);
}
static void transpose_split(const float* in, h16* out, int R, int C, int batch,
                            cudaStream_t st) {
    dim3 g(C / 32, R / 32, batch), b(32, 8);
    transpose16<<<g, b, 0, st>>>(in, out, R, C);
}

extern "C" void kernel_launch(void* const* d_in, const int* in_sizes, int n_in,
                              void* d_out, int out_size)
{
    (void)in_sizes; (void)n_in; (void)out_size;
    const float* tgt     = (const float*)d_in[0];
    const float* memory  = (const float*)d_in[1];
    const float* score_c = (const float*)d_in[2];
    const float* out_c   = (const float*)d_in[3];
    const float* Wq  = (const float*)d_in[4];
    const float* bq  = (const float*)d_in[5];
    const float* Wk  = (const float*)d_in[6];
    const float* Wv  = (const float*)d_in[8];
    const float* bv  = (const float*)d_in[9];
    const float* Wkn = (const float*)d_in[10];
    const float* bkn = (const float*)d_in[11];
    const float* Wun = (const float*)d_in[12];
    const float* bun = (const float*)d_in[13];
    const float* W1  = (const float*)d_in[14];
    const float* b1  = (const float*)d_in[15];
    const float* W2  = (const float*)d_in[16];
    const float* b2  = (const float*)d_in[17];
    const float* g1  = (const float*)d_in[18];
    const float* be1 = (const float*)d_in[19];
    const float* g2  = (const float*)d_in[20];
    const float* be2 = (const float*)d_in[21];

    float *x, *att, *mix, *m2slab, *y2slab, *zslab, *pvec, *wvec;
    SYM(x, g_x); SYM(att, g_att); SYM(mix, g_mix);
    SYM(m2slab, g_m2slab); SYM(y2slab, g_y2slab); SYM(zslab, g_zslab);
    SYM(pvec, g_pvec); SYM(wvec, g_wvec);
    h16 *xh,*qxh,*mh,*unh,*knh,*m2h,*vth,*blh,*hh,*oh,*sth;
    h16 *wqth,*wkth,*wqkth,*wvh,*wnh,*wuh,*w1h,*w2h;
    SYM(xh,g_xh); SYM(qxh,g_qxh); SYM(mh,g_mh);
    SYM(unh,g_unh); SYM(knh,g_knh); SYM(m2h,g_m2h); SYM(vth,g_vth);
    SYM(blh,g_blh); SYM(hh,g_hh); SYM(oh,g_oh); SYM(sth,g_sth);
    SYM(wqth,g_wqth); SYM(wkth,g_wkth); SYM(wqkth,g_wqkth);
    SYM(wvh,g_wvh); SYM(wnh,g_wnh); SYM(wuh,g_wuh);
    SYM(w1h,g_w1h); SYM(w2h,g_w2h);

    cudaFuncSetAttribute(mma_gemm, cudaFuncAttributeMaxDynamicSharedMemorySize, SMEM_DYN);

    // ---- streams/events (created once) ----
    static cudaStream_t s1 = nullptr, s2 = nullptr;
    static cudaEvent_t e0 = nullptr, s1done = nullptr;
    static cudaEvent_t ev_m2t[LY], ev_att[LY], ev_vt[LY], ev_x[LY];
    if (!s1) {
        cudaStreamCreateWithFlags(&s1, cudaStreamNonBlocking);
        cudaStreamCreateWithFlags(&s2, cudaStreamNonBlocking);
        cudaEventCreateWithFlags(&e0, cudaEventDisableTiming);
        cudaEventCreateWithFlags(&s1done, cudaEventDisableTiming);
        for (int l = 0; l < LY; l++) {
            cudaEventCreateWithFlags(&ev_m2t[l], cudaEventDisableTiming);
            cudaEventCreateWithFlags(&ev_att[l], cudaEventDisableTiming);
            cudaEventCreateWithFlags(&ev_vt[l], cudaEventDisableTiming);
            cudaEventCreateWithFlags(&ev_x[l], cudaEventDisableTiming);
        }
    }

    const float scale = 1.0f / sqrtf((float)D_);
    cudaStream_t s0 = 0;

    // ---- prologue (r12 structure; memT no longer needed) ----
    cudaMemcpyAsync(x, tgt, (size_t)NX * 4, cudaMemcpyDeviceToDevice, s0);
    split(tgt, xh, NX, s0);
    split(memory, mh, NMEM, s0);
    split(out_c, oh, NOC, s0);
    split(Wv, wvh, NWKT, s0);
    split(Wkn, wnh, NWQT, s0);
    split(Wun, wuh, NWQT, s0);
    split(W1, w1h, NW1, s0);
    split(W2, w2h, NW1, s0);
    transpose_split(Wq, wqth, D_, D_, LY, s0);
    transpose_split(Wk, wkth, D_, DK, LY, s0);
    gemm(wkth, wqth, nullptr, 1.f, 0, nullptr, wqkth,
         DK, D_, D_, LY, (long long)DK*D_, (long long)D_*D_, (long long)DK*D_, s0);
    pvec_all<<<LY, DK, 0, s0>>>(Wk, bq, pvec);
    wvec_all<<<LY * (BN*T1/256), 256, 0, s0>>>(memory, pvec, wvec, scale);
    cudaEventRecord(e0, s0);

    // ---- stream s1: x-independent precompute (all layers; gated on e0) ----
    cudaStreamWaitEvent(s1, e0, 0);
    for (int l = 0; l < LY; l++) {
        const long long oq = (long long)l * D_ * D_;
        gemm(wnh + oq, oh + (long long)l*BN*TC*D_, bkn + (long long)l*D_, 1.f, 2,
             nullptr, knh, D_, TC, D_, BN, 0, (long long)TC*D_, (long long)D_*TC, s1);
        transpose_split(score_c + (long long)l*BN*TC*T1, sth, TC, T1, BN, s1);
        gemm(sth, knh, nullptr, scale, 0, m2slab, nullptr,
             T1, D_, TC, BN, (long long)T1*TC, (long long)D_*TC, (long long)T1*D_,
             s1, 2, (long long)NM2);
        reduce16<<<(NM2/4 + 255)/256, 256, 0, s1>>>(
            m2slab, NM2/4, 2, m2h + (long long)l*NM2, NM2/4);
        cudaEventRecord(ev_m2t[l], s1);
    }
    cudaEventRecord(s1done, s1);

    // ---- main + s2 per-layer ----
    for (int l = 0; l < LY; l++) {
        const long long oq = (long long)l * D_ * D_;
        const long long ok = (long long)l * D_ * DK;
        const long long o1 = (long long)l * FF * D_;

        // s2: qx -> att, then vT = Wv@mem^T + bv (row bias; constants only)
        cudaStreamWaitEvent(s2, (l == 0) ? e0 : ev_x[l], 0);
        gemm(xh, wqkth + ok, nullptr, 1.f, 0, nullptr, qxh,
             BN*T_, DK, D_, 1, 0, 0, 0, s2);
        gemm(qxh, mh, nullptr, scale, 0, att, nullptr,
             T_, T1, DK, BN, (long long)T_*DK, (long long)T1*DK, (long long)T_*T1, s2);
        cudaEventRecord(ev_att[l], s2);
        gemm(wvh + ok, mh, bv + (long long)l*D_, 1.f, 2, nullptr, vth,
             D_, T1, DK, BN, 0, (long long)T1*DK, (long long)D_*T1, s2);
        cudaEventRecord(ev_vt[l], s2);

        // main: unk
        gemm(xh, wuh + oq, bun + (long long)l*D_, 1.f, 0, nullptr, unh,
             BN*T_, D_, D_, 1, 0, 0, 0, s0);
        // main: mixed (needs M2T[l])
        cudaStreamWaitEvent(s0, ev_m2t[l], 0);
        gemm(unh, m2h + (long long)l*NM2, nullptr, 1.f, 0, mix, nullptr,
             T_, T1, D_, BN, (long long)T_*D_, (long long)T1*D_, (long long)T_*T1, s0);
        // main: softmax blend (needs att)
        cudaStreamWaitEvent(s0, ev_att[l], 0);
        softmax_blend<<<BN*T_, 256, 0, s0>>>(mix, att, wvec + (long long)l*BN*T1, blh);
        // z_b = blended_b @ vT_b^T : [T, D], split-K=4 (bv folded into vT)
        cudaStreamWaitEvent(s0, ev_vt[l], 0);
        gemm(blh, vth, nullptr, 1.f, 0, zslab, nullptr,
             T_, D_, T1, BN, (long long)T_*T1, (long long)D_*T1, (long long)T_*D_,
             s0, 4, (long long)NX);
        add_ln<<<BN*T_, 128, 0, s0>>>(x, zslab, 4, (long long)NX, nullptr,
                                      g1 + (long long)l*D_, be1 + (long long)l*D_, xh);
        // h = relu(x @ W1^T + b1)
        gemm(xh, w1h + o1, b1 + (long long)l*FF, 1.f, 1, nullptr, hh,
             BN*T_, FF, D_, 1, 0, 0, 0, s0);
        // y2 = h @ W2^T, split-K=3 (b2 added in add_ln)
        gemm(hh, w2h + o1, nullptr, 1.f, 0, y2slab, nullptr,
             BN*T_, D_, FF, 1, 0, 0, 0, s0, 3, (long long)NX);
        add_ln<<<BN*T_, 128, 0, s0>>>(x, y2slab, 3, (long long)NX, b2 + (long long)l*D_,
                                      g2 + (long long)l*D_, be2 + (long long)l*D_, xh);
        if (l + 1 < LY) cudaEventRecord(ev_x[l + 1], s0);
    }

    cudaStreamWaitEvent(s0, s1done, 0);
    cudaMemcpyAsync(d_out, x, (size_t)NX * 4, cudaMemcpyDeviceToDevice, s0);
}